// round 15
// baseline (speedup 1.0000x reference)
#include <cuda_runtime.h>
#include <cuda_bf16.h>

#define N_NODES 50000
#define N_EDGES 800000
#define HID 64
#define IN_DIM 4
#define BN_EPS 1e-5f

#define GRID_T ((N_NODES + 63) / 64)        // 782 64-node tiles
#define GRID_E ((N_EDGES + 255) / 256)      // 3125 edge blocks
static_assert(N_NODES < 65536, "src must fit in 16 bits");

// ---------------- scratch (static device globals; no allocation) ----------------
// Symbols passed as kernel args from host MUST be resolved with
// cudaGetSymbolAddress (bare symbol = host shadow; ATS silently reads host BSS).
__device__ __align__(16) int      g_deg[N_NODES];        // zeroed by fill path for next replay
__device__ __align__(16) float    g_dinv[N_NODES];
__device__ __align__(16) int      g_rowptr[N_NODES + 1];
__device__ __align__(16) int      g_cursor[N_NODES];
__device__ __align__(16) unsigned g_sw[N_EDGES];         // src<<16 | bf16(w)
__device__ __align__(16) float    g_h[N_NODES * HID];    // fp32 residual stream
__device__ __align__(16) uint2    g_hwb[N_NODES * 16];   // bf16 message matrix: 16 x bf16x4 per row

// ================= kernel 0: fused in_proj (node tiles) + count_deg (edge blocks) ==========
__global__ void in_count_kernel(const float* __restrict__ x,
                                const float* __restrict__ W_in,
                                const float* __restrict__ b_in,
                                const int* __restrict__ edge_index) {
    if (blockIdx.x < GRID_T) {
        // ---- input projection: h = x @ W_in + b_in (64 nodes/block) ----
        __shared__ float xs[64 * IN_DIM];
        __shared__ float Ws[IN_DIM * HID];
        __shared__ float bs[HID];
        int tid = threadIdx.x;
        int n0 = blockIdx.x * 64;

        if (tid < IN_DIM * HID) Ws[tid] = W_in[tid];
        if (tid < HID) bs[tid] = b_in[tid];
        {
            int node = n0 + (tid >> 2);
            xs[tid] = (node < N_NODES) ? x[n0 * IN_DIM + tid] : 0.f;
        }
        __syncthreads();

        int j = tid & 63;
        int ng = tid >> 6;
        float bj = bs[j];
        float w0 = Ws[0 * HID + j], w1 = Ws[1 * HID + j], w2 = Ws[2 * HID + j], w3 = Ws[3 * HID + j];
        #pragma unroll 4
        for (int nn = 0; nn < 16; nn++) {
            int nloc = ng * 16 + nn;
            int node = n0 + nloc;
            if (node < N_NODES) {
                const float* xr = &xs[nloc * IN_DIM];
                g_h[node * HID + j] = bj + xr[0] * w0 + xr[1] * w1 + xr[2] * w2 + xr[3] * w3;
            }
        }
    } else {
        // ---- count in-degrees ----
        int e = (blockIdx.x - GRID_T) * 256 + threadIdx.x;
        if (e < N_EDGES) {
            int dst = edge_index[N_EDGES + e];   // row 1 of [2, E]
            atomicAdd(&g_deg[dst], 1);
        }
    }
}

// ================= kernel 1: single-block full scan (rowptr/cursor) + dinv =================
__global__ void scan_all_kernel() {
    __shared__ int buf[2][1024];
    int t = threadIdx.x;
    const int CHUNK = (N_NODES + 1023) / 1024;   // 49
    int base = t * CHUNK;

    // per-thread serial sum over its chunk (+ fused dinv)
    int s = 0;
    for (int i = 0; i < CHUNK; i++) {
        int idx = base + i;
        if (idx < N_NODES) {
            int d = g_deg[idx];
            s += d;
            g_dinv[idx] = rsqrtf((float)(d + 1));   // +1 self loop
        }
    }
    buf[0][t] = s;
    int cur = 0;
    __syncthreads();

    // Hillis-Steele inclusive scan over the 1024 thread sums (double-buffered)
    #pragma unroll
    for (int off = 1; off < 1024; off <<= 1) {
        int v = buf[cur][t];
        if (t >= off) v += buf[cur][t - off];
        buf[1 - cur][t] = v;
        cur ^= 1;
        __syncthreads();
    }

    int run = (t > 0) ? buf[cur][t - 1] : 0;     // exclusive prefix of this chunk
    for (int i = 0; i < CHUNK; i++) {
        int idx = base + i;
        if (idx < N_NODES) {
            g_rowptr[idx] = run;
            g_cursor[idx] = run;
            run += g_deg[idx];
        }
    }
    if (t == 1023) g_rowptr[N_NODES] = buf[cur][1023];
}

// ---- gemm body (R11 measured-best config: 64 nodes/block, 256 thr, 4x4 blocking) ----
__device__ __forceinline__ void gemm_tile_body(int tile, const float* __restrict__ A,
                                               const float* __restrict__ W,
                                               uint2* __restrict__ C,
                                               float* hT, float* Ws) {
    int tid = threadIdx.x;
    int n0 = tile * 64;

    {
        const float4* W4 = (const float4*)W;
        float4* Ws4 = (float4*)Ws;
        #pragma unroll
        for (int i = tid; i < 1024; i += 256) Ws4[i] = W4[i];
    }
    {
        int nn = tid & 63;
        int kq4 = tid >> 6;
        int node = n0 + nn;
        const float4* A4 = (const float4*)A;
        #pragma unroll
        for (int q = 0; q < 4; q++) {
            int kq = kq4 * 4 + q;
            float4 hv = (node < N_NODES) ? A4[node * 16 + kq]
                                         : make_float4(0.f, 0.f, 0.f, 0.f);
            hT[(kq * 4 + 0) * 68 + nn] = hv.x;
            hT[(kq * 4 + 1) * 68 + nn] = hv.y;
            hT[(kq * 4 + 2) * 68 + nn] = hv.z;
            hT[(kq * 4 + 3) * 68 + nn] = hv.w;
        }
    }
    __syncthreads();

    int nq = tid & 15;
    int jq = tid >> 4;
    const float4* Ws4 = (const float4*)Ws;

    float4 acc0 = make_float4(0.f, 0.f, 0.f, 0.f);
    float4 acc1 = acc0, acc2 = acc0, acc3 = acc0;
    #pragma unroll
    for (int k = 0; k < 64; k++) {
        float4 wv = Ws4[k * 16 + jq];
        float4 hv = *(const float4*)&hT[k * 68 + nq * 4];
        acc0.x += hv.x * wv.x; acc0.y += hv.x * wv.y; acc0.z += hv.x * wv.z; acc0.w += hv.x * wv.w;
        acc1.x += hv.y * wv.x; acc1.y += hv.y * wv.y; acc1.z += hv.y * wv.z; acc1.w += hv.y * wv.w;
        acc2.x += hv.z * wv.x; acc2.y += hv.z * wv.y; acc2.z += hv.z * wv.z; acc2.w += hv.z * wv.w;
        acc3.x += hv.w * wv.x; acc3.y += hv.w * wv.y; acc3.z += hv.w * wv.z; acc3.w += hv.w * wv.w;
    }

    float4 accs[4] = {acc0, acc1, acc2, acc3};
    #pragma unroll
    for (int ni = 0; ni < 4; ni++) {
        int node = n0 + nq * 4 + ni;
        if (node < N_NODES) {
            float4 r = accs[ni];
            __nv_bfloat162 lo = __floats2bfloat162_rn(r.x, r.y);
            __nv_bfloat162 hi = __floats2bfloat162_rn(r.z, r.w);
            uint2 pk;
            pk.x = *(unsigned int*)&lo;
            pk.y = *(unsigned int*)&hi;
            C[node * 16 + jq] = pk;
        }
    }
}

// ================= kernel 2: fused CSR fill (edge blocks) + gemm layer-1 (node tiles) ======
__global__ void fill_gemm_kernel(const int* __restrict__ edge_index,
                                 const float* __restrict__ A,
                                 const float* __restrict__ W,
                                 uint2* __restrict__ C) {
    __shared__ float hT[64 * 68];
    __shared__ float Ws[64 * 64];
    if (blockIdx.x < GRID_T) {
        gemm_tile_body(blockIdx.x, A, W, C, hT, Ws);
    } else {
        int e = (blockIdx.x - GRID_T) * 256 + threadIdx.x;
        if (e < N_EDGES) {
            int src = edge_index[e];
            int dst = edge_index[N_EDGES + e];
            int pos = atomicAdd(&g_cursor[dst], 1);
            float w = g_dinv[src] * g_dinv[dst];
            unsigned short wb = __bfloat16_as_ushort(__float2bfloat16(w));
            g_sw[pos] = ((unsigned)src << 16) | (unsigned)wb;
        }
        if (e < N_NODES) g_deg[e] = 0;   // reset for next graph replay (deg dead after scan)
    }
}

// ================= plain gemm (layers 2,3) =================
__global__ void gemm64_bf16_kernel(const float* __restrict__ A,
                                   const float* __restrict__ W,
                                   uint2* __restrict__ C) {
    __shared__ float hT[64 * 68];
    __shared__ float Ws[64 * 64];
    gemm_tile_body(blockIdx.x, A, W, C, hT, Ws);
}

// ================= aggregate + BN + ReLU + residual =================
// 16-lane group per node; lane covers 4 features (bf16x4 = uint2 load).
// Packed edge word: src<<16 | bf16(w)  -> ONE shfl per edge.
__global__ void agg_kernel(const float* __restrict__ conv_b,
                           const float* __restrict__ bn_gamma,
                           const float* __restrict__ bn_beta,
                           const float* __restrict__ bn_mean,
                           const float* __restrict__ bn_var) {
    int gidx = (blockIdx.x * blockDim.x + threadIdx.x) >> 4;   // group = node
    int gl = threadIdx.x & 15;                                  // lane in group
    if (gidx >= N_NODES) return;
    int v = gidx;
    unsigned gmask = 0xFFFFu << (threadIdx.x & 16);             // this half-warp

    float4* h4 = (float4*)g_h;

    float dv = g_dinv[v];
    float wself = dv * dv;
    float4 acc;
    {
        uint2 pk = g_hwb[v * 16 + gl];
        float2 lo = __bfloat1622float2(*(__nv_bfloat162*)&pk.x);
        float2 hi = __bfloat1622float2(*(__nv_bfloat162*)&pk.y);
        acc.x = lo.x * wself; acc.y = lo.y * wself;
        acc.z = hi.x * wself; acc.w = hi.y * wself;
    }

    int beg = g_rowptr[v];
    int end = g_rowptr[v + 1];
    int e = beg;
    for (; e + 16 <= end; e += 16) {
        unsigned p = g_sw[e + gl];
        #pragma unroll
        for (int j = 0; j < 16; j++) {
            unsigned u = __shfl_sync(gmask, p, j, 16);
            int s = (int)(u >> 16);
            float w = __bfloat162float(__ushort_as_bfloat16((unsigned short)(u & 0xFFFFu)));
            uint2 pk = g_hwb[s * 16 + gl];
            float2 lo = __bfloat1622float2(*(__nv_bfloat162*)&pk.x);
            float2 hi = __bfloat1622float2(*(__nv_bfloat162*)&pk.y);
            acc.x += lo.x * w; acc.y += lo.y * w;
            acc.z += hi.x * w; acc.w += hi.y * w;
        }
    }
    if (e < end) {
        int idx = e + gl;
        unsigned p = (idx < end) ? g_sw[idx] : 0u;
        int cnt = end - e;
        for (int j = 0; j < cnt; j++) {
            unsigned u = __shfl_sync(gmask, p, j, 16);
            int s = (int)(u >> 16);
            float w = __bfloat162float(__ushort_as_bfloat16((unsigned short)(u & 0xFFFFu)));
            uint2 pk = g_hwb[s * 16 + gl];
            float2 lo = __bfloat1622float2(*(__nv_bfloat162*)&pk.x);
            float2 hi = __bfloat1622float2(*(__nv_bfloat162*)&pk.y);
            acc.x += lo.x * w; acc.y += lo.y * w;
            acc.z += hi.x * w; acc.w += hi.y * w;
        }
    }

    float4 cb = ((const float4*)conv_b)[gl];
    float4 gm = ((const float4*)bn_gamma)[gl];
    float4 bt = ((const float4*)bn_beta)[gl];
    float4 mn = ((const float4*)bn_mean)[gl];
    float4 vr = ((const float4*)bn_var)[gl];
    float4 o;
    o.x = fmaxf((acc.x + cb.x - mn.x) * (gm.x * rsqrtf(vr.x + BN_EPS)) + bt.x, 0.f);
    o.y = fmaxf((acc.y + cb.y - mn.y) * (gm.y * rsqrtf(vr.y + BN_EPS)) + bt.y, 0.f);
    o.z = fmaxf((acc.z + cb.z - mn.z) * (gm.z * rsqrtf(vr.z + BN_EPS)) + bt.z, 0.f);
    o.w = fmaxf((acc.w + cb.w - mn.w) * (gm.w * rsqrtf(vr.w + BN_EPS)) + bt.w, 0.f);
    float4 res = h4[v * 16 + gl];
    o.x += res.x; o.y += res.y; o.z += res.z; o.w += res.w;
    h4[v * 16 + gl] = o;
}

// ================= fused output MLP: out = x + relu(h@W1+b1)@W2 + b2 =================
__global__ void out_fused_kernel(const float* __restrict__ A,   // g_h (device ptr)
                                 const float* __restrict__ W1,
                                 const float* __restrict__ b1,
                                 const float* __restrict__ W2,
                                 const float* __restrict__ b2,
                                 const float* __restrict__ x,
                                 float* __restrict__ out) {
    __shared__ float hT[64 * 68];
    __shared__ float Ws[64 * 64];
    __shared__ float ts[64 * 68];
    __shared__ float W2s[HID * IN_DIM];
    __shared__ float b2s[IN_DIM];
    int tid = threadIdx.x;
    int n0 = blockIdx.x * 64;

    {
        const float4* W4 = (const float4*)W1;
        float4* Ws4 = (float4*)Ws;
        #pragma unroll
        for (int i = tid; i < 1024; i += 256) Ws4[i] = W4[i];
    }
    if (tid < HID * IN_DIM) W2s[tid] = W2[tid];
    if (tid < IN_DIM) b2s[tid] = b2[tid];
    {
        int nn = tid & 63;
        int kq4 = tid >> 6;
        int node = n0 + nn;
        const float4* A4 = (const float4*)A;
        #pragma unroll
        for (int q = 0; q < 4; q++) {
            int kq = kq4 * 4 + q;
            float4 hv = (node < N_NODES) ? A4[node * 16 + kq]
                                         : make_float4(0.f, 0.f, 0.f, 0.f);
            hT[(kq * 4 + 0) * 68 + nn] = hv.x;
            hT[(kq * 4 + 1) * 68 + nn] = hv.y;
            hT[(kq * 4 + 2) * 68 + nn] = hv.z;
            hT[(kq * 4 + 3) * 68 + nn] = hv.w;
        }
    }
    __syncthreads();

    int nq = tid & 15;
    int jq = tid >> 4;
    const float4* Ws4 = (const float4*)Ws;

    float4 acc0 = make_float4(0.f, 0.f, 0.f, 0.f);
    float4 acc1 = acc0, acc2 = acc0, acc3 = acc0;
    #pragma unroll
    for (int k = 0; k < 64; k++) {
        float4 wv = Ws4[k * 16 + jq];
        float4 hv = *(const float4*)&hT[k * 68 + nq * 4];
        acc0.x += hv.x * wv.x; acc0.y += hv.x * wv.y; acc0.z += hv.x * wv.z; acc0.w += hv.x * wv.w;
        acc1.x += hv.y * wv.x; acc1.y += hv.y * wv.y; acc1.z += hv.y * wv.z; acc1.w += hv.y * wv.w;
        acc2.x += hv.z * wv.x; acc2.y += hv.z * wv.y; acc2.z += hv.z * wv.z; acc2.w += hv.z * wv.w;
        acc3.x += hv.w * wv.x; acc3.y += hv.w * wv.y; acc3.z += hv.w * wv.z; acc3.w += hv.w * wv.w;
    }

    float4 bv = ((const float4*)b1)[jq];
    float4 accs[4] = {acc0, acc1, acc2, acc3};
    #pragma unroll
    for (int ni = 0; ni < 4; ni++) {
        int nloc = nq * 4 + ni;
        float4 r = accs[ni];
        r.x = fmaxf(r.x + bv.x, 0.f);
        r.y = fmaxf(r.y + bv.y, 0.f);
        r.z = fmaxf(r.z + bv.z, 0.f);
        r.w = fmaxf(r.w + bv.w, 0.f);
        *(float4*)&ts[nloc * 68 + jq * 4] = r;
    }
    __syncthreads();

    int nloc = tid >> 2;
    int m = tid & 3;
    int node = n0 + nloc;
    float acc = 0.f;
    #pragma unroll
    for (int l = 0; l < 64; l++) {
        acc += ts[nloc * 68 + l] * W2s[l * IN_DIM + m];
    }
    if (node < N_NODES) {
        out[node * IN_DIM + m] = x[node * IN_DIM + m] + b2s[m] + acc;
    }
}

// ---------------- launch (9 kernels total) ----------------
extern "C" void kernel_launch(void* const* d_in, const int* in_sizes, int n_in,
                              void* d_out, int out_size) {
    const float* x          = (const float*)d_in[0];
    const int*   edge_index = (const int*)d_in[1];
    const float* W_in       = (const float*)d_in[2];
    const float* b_in       = (const float*)d_in[3];
    const float* conv_w     = (const float*)d_in[4];   // [3,64,64]
    const float* conv_b     = (const float*)d_in[5];   // [3,64]
    const float* bn_gamma   = (const float*)d_in[6];
    const float* bn_beta    = (const float*)d_in[7];
    const float* bn_mean    = (const float*)d_in[8];
    const float* bn_var     = (const float*)d_in[9];
    const float* W1         = (const float*)d_in[10];
    const float* b1         = (const float*)d_in[11];
    const float* W2         = (const float*)d_in[12];
    const float* b2         = (const float*)d_in[13];
    float* out = (float*)d_out;

    void* p_h = nullptr;
    void* p_hwb = nullptr;
    cudaGetSymbolAddress(&p_h, g_h);
    cudaGetSymbolAddress(&p_hwb, g_hwb);
    float* d_h = (float*)p_h;
    uint2* d_hwb = (uint2*)p_hwb;

    const int TPB = 256;
    const int gridG = (N_NODES * 16 + TPB - 1) / TPB;     // 16-lane group per node

    // 0: in_proj + count_deg (independent work, one grid)
    in_count_kernel<<<GRID_T + GRID_E, TPB>>>(x, W_in, b_in, edge_index);
    // 1: full prefix scan + dinv (single block)
    scan_all_kernel<<<1, 1024>>>();
    // 2: CSR fill + gemm layer-1 (independent work, one grid)
    fill_gemm_kernel<<<GRID_T + GRID_E, TPB>>>(edge_index, d_h, conv_w + 0 * HID * HID, d_hwb);
    // 3: agg layer-1  <- profiled launch index 3
    agg_kernel<<<gridG, TPB>>>(conv_b + 0 * HID,
                               bn_gamma + 0 * HID, bn_beta + 0 * HID,
                               bn_mean + 0 * HID, bn_var + 0 * HID);
    // 4..7: layers 2,3
    for (int i = 1; i < 3; i++) {
        gemm64_bf16_kernel<<<GRID_T, TPB>>>(d_h, conv_w + i * HID * HID, d_hwb);
        agg_kernel<<<gridG, TPB>>>(conv_b + i * HID,
                                   bn_gamma + i * HID, bn_beta + i * HID,
                                   bn_mean + i * HID, bn_var + i * HID);
    }
    // 8: fused output MLP + residual
    out_fused_kernel<<<GRID_T, TPB>>>(d_h, W1, b1, W2, b2, x, out);
}

// round 16
// speedup vs baseline: 2.0114x; 2.0114x over previous
#include <cuda_runtime.h>
#include <cuda_bf16.h>
#include <cstdint>

#define N_NODES 50000
#define N_EDGES 800000
#define HID 64
#define IN_DIM 4
#define BN_EPS 1e-5f

#define SCAN_BLK 256
#define NBLK ((N_NODES + SCAN_BLK - 1) / SCAN_BLK)   // 196
static_assert(NBLK <= 256, "NBLK must fit one scan block");
static_assert(N_NODES < 65536, "src must fit in 16 bits");

// ---------------- scratch (static device globals; no allocation) ----------------
// Symbols passed as kernel args from host MUST be resolved with
// cudaGetSymbolAddress (bare symbol = host shadow; ATS silently reads host BSS).
__device__ __align__(16) int      g_deg[N_NODES];        // zeroed by fill_kernel for next replay
__device__ __align__(16) float    g_dinv[N_NODES];
__device__ __align__(16) int      g_rowptr[N_NODES + 1];
__device__ __align__(16) int      g_cursor[N_NODES];
__device__ __align__(16) unsigned g_sw[N_EDGES];         // src<<16 | bf16(w)
__device__ __align__(16) float    g_h[N_NODES * HID];    // fp32 residual stream
__device__ __align__(16) uint2    g_hwb[N_NODES * 16];   // bf16 message matrix: 16 x bf16x4 per row

// ---------------- graph preprocessing ----------------
__global__ void count_deg_kernel(const int* __restrict__ edge_index) {
    int e = blockIdx.x * blockDim.x + threadIdx.x;
    if (e < N_EDGES) {
        int dst = edge_index[N_EDGES + e];   // row 1 of [2, E]
        atomicAdd(&g_deg[dst], 1);
    }
}

__device__ __align__(16) int g_blocksum[NBLK];
__device__ __align__(16) int g_blockoff[NBLK];

// stage 1: per-block tree reduction of degrees (+ fused dinv)
__global__ void scan_reduce_kernel() {
    __shared__ int sdata[SCAN_BLK];
    int b = blockIdx.x, t = threadIdx.x;
    int i = b * SCAN_BLK + t;
    int d = (i < N_NODES) ? g_deg[i] : 0;
    if (i < N_NODES) g_dinv[i] = rsqrtf((float)(d + 1));  // +1 self loop
    sdata[t] = d;
    __syncthreads();
    #pragma unroll
    for (int s = SCAN_BLK / 2; s > 0; s >>= 1) {
        if (t < s) sdata[t] += sdata[t + s];
        __syncthreads();
    }
    if (t == 0) g_blocksum[b] = sdata[0];
}

// stage 2: one block scans the block sums (double-buffered)
__global__ void scan_offsets_kernel() {
    __shared__ int buf[2][256];
    int t = threadIdx.x;
    buf[0][t] = (t < NBLK) ? g_blocksum[t] : 0;
    int cur = 0;
    __syncthreads();
    #pragma unroll
    for (int off = 1; off < 256; off <<= 1) {
        int x = buf[cur][t];
        if (t >= off) x += buf[cur][t - off];
        buf[1 - cur][t] = x;
        cur = 1 - cur;
        __syncthreads();
    }
    if (t < NBLK) g_blockoff[t] = (t > 0) ? buf[cur][t - 1] : 0;
    if (t == NBLK - 1) g_rowptr[N_NODES] = buf[cur][t];
}

// stage 3: per-block scan of degrees + write rowptr/cursor
__global__ void scan_write_kernel() {
    __shared__ int buf[2][SCAN_BLK];
    int b = blockIdx.x, t = threadIdx.x;
    int i = b * SCAN_BLK + t;
    int v = (i < N_NODES) ? g_deg[i] : 0;
    buf[0][t] = v;
    int cur = 0;
    __syncthreads();
    #pragma unroll
    for (int off = 1; off < SCAN_BLK; off <<= 1) {
        int x = buf[cur][t];
        if (t >= off) x += buf[cur][t - off];
        buf[1 - cur][t] = x;
        cur = 1 - cur;
        __syncthreads();
    }
    int incl = buf[cur][t];
    int excl = incl - v + g_blockoff[b];
    if (i < N_NODES) {
        g_rowptr[i] = excl;
        g_cursor[i] = excl;
    }
}

// fill CSR; also re-zero g_deg for the next graph replay (deg is dead after scan_write)
__global__ void fill_kernel(const int* __restrict__ edge_index) {
    int e = blockIdx.x * blockDim.x + threadIdx.x;
    if (e < N_EDGES) {
        int src = edge_index[e];
        int dst = edge_index[N_EDGES + e];
        int pos = atomicAdd(&g_cursor[dst], 1);
        float w = g_dinv[src] * g_dinv[dst];
        unsigned short wb = __bfloat16_as_ushort(__float2bfloat16(w));
        g_sw[pos] = ((unsigned)src << 16) | (unsigned)wb;
    }
    if (e < N_NODES) g_deg[e] = 0;
}

// ---------------- input projection: h = x @ W_in + b_in ----------------
__global__ void in_proj_kernel(const float* __restrict__ x,
                               const float* __restrict__ W_in,
                               const float* __restrict__ b_in) {
    __shared__ float xs[64 * IN_DIM];
    __shared__ float Ws[IN_DIM * HID];
    __shared__ float bs[HID];
    int tid = threadIdx.x;
    int n0 = blockIdx.x * 64;

    if (tid < IN_DIM * HID) Ws[tid] = W_in[tid];
    if (tid < HID) bs[tid] = b_in[tid];
    {
        int node = n0 + (tid >> 2);
        xs[tid] = (node < N_NODES) ? x[n0 * IN_DIM + tid] : 0.f;
    }
    __syncthreads();

    int j = tid & 63;
    int ng = tid >> 6;
    float bj = bs[j];
    float w0 = Ws[0 * HID + j], w1 = Ws[1 * HID + j], w2 = Ws[2 * HID + j], w3 = Ws[3 * HID + j];
    #pragma unroll 4
    for (int nn = 0; nn < 16; nn++) {
        int nloc = ng * 16 + nn;
        int node = n0 + nloc;
        if (node < N_NODES) {
            const float* xr = &xs[nloc * IN_DIM];
            g_h[node * HID + j] = bj + xr[0] * w0 + xr[1] * w1 + xr[2] * w2 + xr[3] * w3;
        }
    }
}

// ---------------- HMMA 64x64 GEMM: hwb = bf16(A @ W) ----------------
// 64 nodes/block, 256 threads (8 warps). mma.sync m16n8k16 bf16, fp32 accum.
// Warp w: m-block = w%4 (16 rows), n-half = w/4 (32 cols = 4 n-tiles of 8).
#define AS_STRIDE 72   // bf16 per row (64 + 8 pad) -> 144B rows, every 8-col chunk 16B-aligned

__device__ __forceinline__ uint32_t smem_u32(const void* p) {
    return (uint32_t)__cvta_generic_to_shared(p);
}

__global__ void gemm64_bf16_kernel(const float* __restrict__ A,
                                   const float* __restrict__ W,
                                   uint2* __restrict__ C) {
    __shared__ __nv_bfloat16 As[64 * AS_STRIDE];   // [node][k]
    __shared__ __nv_bfloat16 Wt[64 * AS_STRIDE];   // [j][k]  (= W^T)
    int tid = threadIdx.x;
    int lane = tid & 31;
    int warp = tid >> 5;
    int n0 = blockIdx.x * 64;

    // ---- stage A: fp32 -> bf16, [node][k] ----
    {
        int nn = tid & 63;           // node in tile
        int qg = tid >> 6;           // 0..3
        int node = n0 + nn;
        const float4* A4 = (const float4*)A;
        #pragma unroll
        for (int i = 0; i < 4; i++) {
            int kq = qg + 4 * i;     // 0..15, 4 k's each
            float4 hv = (node < N_NODES) ? A4[node * 16 + kq]
                                         : make_float4(0.f, 0.f, 0.f, 0.f);
            __nv_bfloat162 lo = __floats2bfloat162_rn(hv.x, hv.y);
            __nv_bfloat162 hi = __floats2bfloat162_rn(hv.z, hv.w);
            uint2 pk;
            pk.x = *(unsigned int*)&lo;
            pk.y = *(unsigned int*)&hi;
            *(uint2*)&As[nn * AS_STRIDE + kq * 4] = pk;
        }
    }
    // ---- stage W^T: Wt[j][k] = bf16(W[k][j]) ----
    {
        int j = tid & 63;
        int kg = tid >> 6;           // 0..3
        #pragma unroll
        for (int i = 0; i < 16; i++) {
            int k = kg * 16 + i;
            Wt[j * AS_STRIDE + k] = __float2bfloat16(W[k * 64 + j]);
        }
    }
    __syncthreads();

    int mb = warp & 3;               // m-block: rows mb*16..+15
    int nh = warp >> 2;              // n-half: cols nh*32..+31

    float c[4][4];
    #pragma unroll
    for (int t = 0; t < 4; t++)
        #pragma unroll
        for (int r = 0; r < 4; r++) c[t][r] = 0.f;

    #pragma unroll
    for (int ks = 0; ks < 4; ks++) {
        // A fragment: 16x16 at rows mb*16, cols ks*16
        uint32_t a0, a1, a2, a3;
        {
            uint32_t addr = smem_u32(&As[(mb * 16 + (lane & 15)) * AS_STRIDE
                                         + ks * 16 + (lane >> 4) * 8]);
            asm volatile("ldmatrix.sync.aligned.m8n8.x4.shared.b16 {%0,%1,%2,%3}, [%4];"
                         : "=r"(a0), "=r"(a1), "=r"(a2), "=r"(a3) : "r"(addr));
        }
        // B fragments: two ldmatrix.x4, each covering 16 j-rows x 16 k
        #pragma unroll
        for (int pair = 0; pair < 2; pair++) {
            int j0 = nh * 32 + pair * 16;
            uint32_t b0, b1, b2, b3;
            uint32_t addr = smem_u32(&Wt[(j0 + (lane & 15)) * AS_STRIDE
                                         + ks * 16 + (lane >> 4) * 8]);
            asm volatile("ldmatrix.sync.aligned.m8n8.x4.shared.b16 {%0,%1,%2,%3}, [%4];"
                         : "=r"(b0), "=r"(b1), "=r"(b2), "=r"(b3) : "r"(addr));
            // n-tile (pair*2):   frags {b0, b2}   (j0..j0+7)
            // n-tile (pair*2+1): frags {b1, b3}   (j0+8..j0+15)
            int t0 = pair * 2;
            asm volatile("mma.sync.aligned.m16n8k16.row.col.f32.bf16.bf16.f32 "
                         "{%0,%1,%2,%3}, {%4,%5,%6,%7}, {%8,%9}, {%0,%1,%2,%3};"
                         : "+f"(c[t0][0]), "+f"(c[t0][1]), "+f"(c[t0][2]), "+f"(c[t0][3])
                         : "r"(a0), "r"(a1), "r"(a2), "r"(a3), "r"(b0), "r"(b2));
            asm volatile("mma.sync.aligned.m16n8k16.row.col.f32.bf16.bf16.f32 "
                         "{%0,%1,%2,%3}, {%4,%5,%6,%7}, {%8,%9}, {%0,%1,%2,%3};"
                         : "+f"(c[t0+1][0]), "+f"(c[t0+1][1]), "+f"(c[t0+1][2]), "+f"(c[t0+1][3])
                         : "r"(a0), "r"(a1), "r"(a2), "r"(a3), "r"(b1), "r"(b3));
        }
    }

    // ---- epilogue: fragment -> bf16x2 stores ----
    // c[t]: rows mb*16 + lane/4 (+8), cols nh*32 + t*8 + (lane%4)*2
    __nv_bfloat162* Cb2 = (__nv_bfloat162*)C;    // 32 bf16x2 per node row
    int r0 = mb * 16 + (lane >> 2);
    int colq = (lane & 3);
    #pragma unroll
    for (int t = 0; t < 4; t++) {
        int col = nh * 32 + t * 8 + colq * 2;
        int node0 = n0 + r0;
        int node1 = node0 + 8;
        if (node0 < N_NODES)
            Cb2[node0 * 32 + (col >> 1)] = __floats2bfloat162_rn(c[t][0], c[t][1]);
        if (node1 < N_NODES)
            Cb2[node1 * 32 + (col >> 1)] = __floats2bfloat162_rn(c[t][2], c[t][3]);
    }
}

// ---------------- aggregate + BN + ReLU + residual ----------------
// 16-lane group per node; lane covers 4 features (bf16x4 = uint2 load).
// Packed edge word: src<<16 | bf16(w)  -> ONE shfl per edge.
__global__ void agg_kernel(const float* __restrict__ conv_b,
                           const float* __restrict__ bn_gamma,
                           const float* __restrict__ bn_beta,
                           const float* __restrict__ bn_mean,
                           const float* __restrict__ bn_var) {
    int gidx = (blockIdx.x * blockDim.x + threadIdx.x) >> 4;   // group = node
    int gl = threadIdx.x & 15;                                  // lane in group
    if (gidx >= N_NODES) return;
    int v = gidx;
    unsigned gmask = 0xFFFFu << (threadIdx.x & 16);             // this half-warp

    float4* h4 = (float4*)g_h;

    float dv = g_dinv[v];
    float wself = dv * dv;
    float4 acc;
    {
        uint2 pk = g_hwb[v * 16 + gl];
        float2 lo = __bfloat1622float2(*(__nv_bfloat162*)&pk.x);
        float2 hi = __bfloat1622float2(*(__nv_bfloat162*)&pk.y);
        acc.x = lo.x * wself; acc.y = lo.y * wself;
        acc.z = hi.x * wself; acc.w = hi.y * wself;
    }

    int beg = g_rowptr[v];
    int end = g_rowptr[v + 1];
    int e = beg;
    for (; e + 16 <= end; e += 16) {
        unsigned p = g_sw[e + gl];
        #pragma unroll
        for (int j = 0; j < 16; j++) {
            unsigned u = __shfl_sync(gmask, p, j, 16);
            int s = (int)(u >> 16);
            float w = __bfloat162float(__ushort_as_bfloat16((unsigned short)(u & 0xFFFFu)));
            uint2 pk = g_hwb[s * 16 + gl];
            float2 lo = __bfloat1622float2(*(__nv_bfloat162*)&pk.x);
            float2 hi = __bfloat1622float2(*(__nv_bfloat162*)&pk.y);
            acc.x += lo.x * w; acc.y += lo.y * w;
            acc.z += hi.x * w; acc.w += hi.y * w;
        }
    }
    if (e < end) {
        int idx = e + gl;
        unsigned p = (idx < end) ? g_sw[idx] : 0u;
        int cnt = end - e;
        for (int j = 0; j < cnt; j++) {
            unsigned u = __shfl_sync(gmask, p, j, 16);
            int s = (int)(u >> 16);
            float w = __bfloat162float(__ushort_as_bfloat16((unsigned short)(u & 0xFFFFu)));
            uint2 pk = g_hwb[s * 16 + gl];
            float2 lo = __bfloat1622float2(*(__nv_bfloat162*)&pk.x);
            float2 hi = __bfloat1622float2(*(__nv_bfloat162*)&pk.y);
            acc.x += lo.x * w; acc.y += lo.y * w;
            acc.z += hi.x * w; acc.w += hi.y * w;
        }
    }

    float4 cb = ((const float4*)conv_b)[gl];
    float4 gm = ((const float4*)bn_gamma)[gl];
    float4 bt = ((const float4*)bn_beta)[gl];
    float4 mn = ((const float4*)bn_mean)[gl];
    float4 vr = ((const float4*)bn_var)[gl];
    float4 o;
    o.x = fmaxf((acc.x + cb.x - mn.x) * (gm.x * rsqrtf(vr.x + BN_EPS)) + bt.x, 0.f);
    o.y = fmaxf((acc.y + cb.y - mn.y) * (gm.y * rsqrtf(vr.y + BN_EPS)) + bt.y, 0.f);
    o.z = fmaxf((acc.z + cb.z - mn.z) * (gm.z * rsqrtf(vr.z + BN_EPS)) + bt.z, 0.f);
    o.w = fmaxf((acc.w + cb.w - mn.w) * (gm.w * rsqrtf(vr.w + BN_EPS)) + bt.w, 0.f);
    float4 res = h4[v * 16 + gl];
    o.x += res.x; o.y += res.y; o.z += res.z; o.w += res.w;
    h4[v * 16 + gl] = o;
}

// ---------------- fused output MLP: out = x + relu(h@W1+b1)@W2 + b2 ----------------
__global__ void out_fused_kernel(const float* __restrict__ A,   // g_h (device ptr)
                                 const float* __restrict__ W1,
                                 const float* __restrict__ b1,
                                 const float* __restrict__ W2,
                                 const float* __restrict__ b2,
                                 const float* __restrict__ x,
                                 float* __restrict__ out) {
    __shared__ float hT[64 * 68];
    __shared__ float Ws[64 * 64];
    __shared__ float ts[64 * 68];
    __shared__ float W2s[HID * IN_DIM];
    __shared__ float b2s[IN_DIM];
    int tid = threadIdx.x;
    int n0 = blockIdx.x * 64;

    {
        const float4* W4 = (const float4*)W1;
        float4* Ws4 = (float4*)Ws;
        #pragma unroll
        for (int i = tid; i < 1024; i += 256) Ws4[i] = W4[i];
    }
    if (tid < HID * IN_DIM) W2s[tid] = W2[tid];
    if (tid < IN_DIM) b2s[tid] = b2[tid];
    {
        int nn = tid & 63;
        int kq4 = tid >> 6;
        int node = n0 + nn;
        const float4* A4 = (const float4*)A;
        #pragma unroll
        for (int q = 0; q < 4; q++) {
            int kq = kq4 * 4 + q;
            float4 hv = (node < N_NODES) ? A4[node * 16 + kq]
                                         : make_float4(0.f, 0.f, 0.f, 0.f);
            hT[(kq * 4 + 0) * 68 + nn] = hv.x;
            hT[(kq * 4 + 1) * 68 + nn] = hv.y;
            hT[(kq * 4 + 2) * 68 + nn] = hv.z;
            hT[(kq * 4 + 3) * 68 + nn] = hv.w;
        }
    }
    __syncthreads();

    int nq = tid & 15;
    int jq = tid >> 4;
    const float4* Ws4 = (const float4*)Ws;

    float4 acc0 = make_float4(0.f, 0.f, 0.f, 0.f);
    float4 acc1 = acc0, acc2 = acc0, acc3 = acc0;
    #pragma unroll
    for (int k = 0; k < 64; k++) {
        float4 wv = Ws4[k * 16 + jq];
        float4 hv = *(const float4*)&hT[k * 68 + nq * 4];
        acc0.x += hv.x * wv.x; acc0.y += hv.x * wv.y; acc0.z += hv.x * wv.z; acc0.w += hv.x * wv.w;
        acc1.x += hv.y * wv.x; acc1.y += hv.y * wv.y; acc1.z += hv.y * wv.z; acc1.w += hv.y * wv.w;
        acc2.x += hv.z * wv.x; acc2.y += hv.z * wv.y; acc2.z += hv.z * wv.z; acc2.w += hv.z * wv.w;
        acc3.x += hv.w * wv.x; acc3.y += hv.w * wv.y; acc3.z += hv.w * wv.z; acc3.w += hv.w * wv.w;
    }

    float4 bv = ((const float4*)b1)[jq];
    float4 accs[4] = {acc0, acc1, acc2, acc3};
    #pragma unroll
    for (int ni = 0; ni < 4; ni++) {
        int nloc = nq * 4 + ni;
        float4 r = accs[ni];
        r.x = fmaxf(r.x + bv.x, 0.f);
        r.y = fmaxf(r.y + bv.y, 0.f);
        r.z = fmaxf(r.z + bv.z, 0.f);
        r.w = fmaxf(r.w + bv.w, 0.f);
        *(float4*)&ts[nloc * 68 + jq * 4] = r;
    }
    __syncthreads();

    int nloc = tid >> 2;
    int m = tid & 3;
    int node = n0 + nloc;
    float acc = 0.f;
    #pragma unroll
    for (int l = 0; l < 64; l++) {
        acc += ts[nloc * 68 + l] * W2s[l * IN_DIM + m];
    }
    if (node < N_NODES) {
        out[node * IN_DIM + m] = x[node * IN_DIM + m] + b2s[m] + acc;
    }
}

// ---------------- launch ----------------
extern "C" void kernel_launch(void* const* d_in, const int* in_sizes, int n_in,
                              void* d_out, int out_size) {
    const float* x          = (const float*)d_in[0];
    const int*   edge_index = (const int*)d_in[1];
    const float* W_in       = (const float*)d_in[2];
    const float* b_in       = (const float*)d_in[3];
    const float* conv_w     = (const float*)d_in[4];   // [3,64,64]
    const float* conv_b     = (const float*)d_in[5];   // [3,64]
    const float* bn_gamma   = (const float*)d_in[6];
    const float* bn_beta    = (const float*)d_in[7];
    const float* bn_mean    = (const float*)d_in[8];
    const float* bn_var     = (const float*)d_in[9];
    const float* W1         = (const float*)d_in[10];
    const float* b1         = (const float*)d_in[11];
    const float* W2         = (const float*)d_in[12];
    const float* b2         = (const float*)d_in[13];
    float* out = (float*)d_out;

    void* p_h = nullptr;
    void* p_hwb = nullptr;
    cudaGetSymbolAddress(&p_h, g_h);
    cudaGetSymbolAddress(&p_hwb, g_hwb);
    float* d_h = (float*)p_h;
    uint2* d_hwb = (uint2*)p_hwb;

    const int TPB = 256;
    const int gridE = (N_EDGES + TPB - 1) / TPB;
    const int gridT = (N_NODES + 63) / 64;                // 64-node tiles
    const int gridG = (N_NODES * 16 + TPB - 1) / TPB;     // 16-lane group per node

    // Launch order puts gemm1 at index 3 so the fixed ncu window profiles it.
    in_proj_kernel<<<gridT, TPB>>>(x, W_in, b_in);                        // 0
    count_deg_kernel<<<gridE, TPB>>>(edge_index);                         // 1
    scan_reduce_kernel<<<NBLK, SCAN_BLK>>>();                             // 2 (also dinv)
    gemm64_bf16_kernel<<<gridT, TPB>>>(d_h, conv_w + 0 * HID * HID, d_hwb); // 3  <- profiled (HMMA)
    scan_offsets_kernel<<<1, 256>>>();                                    // 4
    scan_write_kernel<<<NBLK, SCAN_BLK>>>();                              // 5
    fill_kernel<<<gridE, TPB>>>(edge_index);                              // 6 (also re-zeros deg)

    // layer 1 aggregate
    agg_kernel<<<gridG, TPB>>>(conv_b + 0 * HID,
                               bn_gamma + 0 * HID, bn_beta + 0 * HID,
                               bn_mean + 0 * HID, bn_var + 0 * HID);      // 7

    // layers 2..3
    for (int i = 1; i < 3; i++) {
        gemm64_bf16_kernel<<<gridT, TPB>>>(d_h, conv_w + i * HID * HID, d_hwb);
        agg_kernel<<<gridG, TPB>>>(conv_b + i * HID,
                                   bn_gamma + i * HID, bn_beta + i * HID,
                                   bn_mean + i * HID, bn_var + i * HID);
    }

    // fused output MLP + residual
    out_fused_kernel<<<gridT, TPB>>>(d_h, W1, b1, W2, b2, x, out);
}